// round 7
// baseline (speedup 1.0000x reference)
#include <cuda_runtime.h>
#include <math.h>
#include <stdint.h>

#define BB 8
#define TT 2048
#define DD 1024
#define HS 64

// Q,K: [b][t][h] tf32 bits.  V: TRANSPOSED [b][h][t] tf32 bits.
__device__ uint32_t g_Q[BB * TT * HS];
__device__ uint32_t g_K[BB * TT * HS];
__device__ uint32_t g_V[BB * TT * HS];

// ---------------------------------------------------------------------------
__device__ __forceinline__ uint32_t f2tf(float f) {
    uint32_t u;
    asm("cvt.rna.tf32.f32 %0, %1;" : "=r"(u) : "f"(f));
    return u;
}

__device__ __forceinline__ void mma_tf32(float* d,
                                         uint32_t a0, uint32_t a1, uint32_t a2, uint32_t a3,
                                         uint32_t b0, uint32_t b1) {
    asm volatile(
        "mma.sync.aligned.m16n8k8.row.col.f32.tf32.tf32.f32 "
        "{%0,%1,%2,%3}, {%4,%5,%6,%7}, {%8,%9}, {%0,%1,%2,%3};\n"
        : "+f"(d[0]), "+f"(d[1]), "+f"(d[2]), "+f"(d[3])
        : "r"(a0), "r"(a1), "r"(a2), "r"(a3), "r"(b0), "r"(b1));
}

#define LDSM_X4(r0, r1, r2, r3, addr) \
    asm volatile("ldmatrix.sync.aligned.m8n8.x4.shared.b16 {%0,%1,%2,%3}, [%4];" \
                 : "=r"(r0), "=r"(r1), "=r"(r2), "=r"(r3) : "r"(addr))

#define CP_ASYNC16(dst_bytes, src_ptr) \
    asm volatile("cp.async.cg.shared.global [%0], [%1], 16;\n" \
                 :: "r"(dst_bytes), "l"(src_ptr))
#define CP_COMMIT() asm volatile("cp.async.commit_group;\n" ::: "memory")
#define CP_WAIT(n)  asm volatile("cp.async.wait_group %0;\n" :: "n"(n) : "memory")

#define BARH(id) asm volatile("bar.sync %0, 256;" :: "r"(id) : "memory")

// ---------------------------------------------------------------------------
// Kernel 1: fused QKV projection as ONE GEMM: [16384 x 1024] x [1024 x 192].
// Grid 128, block tile m=128 x n=192(Q|K|V), 512 threads = 16 warps.
// Warp grid 4(m) x 4(n): warp tile 32 x 48 (2 m-frags x 6 n-frags).
// Double-buffered smem (one __syncthreads per k-chunk of 32).
// xs pitch 36 (ldsm rows 4 banks apart); ws pitch 196 (B LDS banks 4t4+g).
// ---------------------------------------------------------------------------
#define PXS_P 36
#define PWS_P 196
#define POFF_W (2 * 128 * PXS_P)
#define PSMEM_U32 (POFF_W + 2 * 32 * PWS_P)
#define PSMEM_BYTES (PSMEM_U32 * 4)

__global__ __launch_bounds__(512, 1) void qkv_proj(
    const float* __restrict__ x,
    const float* __restrict__ Wq, const float* __restrict__ bq,
    const float* __restrict__ Wk, const float* __restrict__ bk,
    const float* __restrict__ Wv, const float* __restrict__ bv) {
    extern __shared__ uint32_t psm[];
    uint32_t* xs = psm;                 // [2][128][PXS_P]
    uint32_t* ws = psm + POFF_W;        // [2][32][PWS_P]
    const uint32_t smb = (uint32_t)__cvta_generic_to_shared(psm);

    const int tid  = threadIdx.x;
    const int lane = tid & 31;
    const int wid  = tid >> 5;          // 0..15
    const int wm   = wid & 3;           // m band (32 rows)
    const int wn   = wid >> 2;          // n band (48 cols)
    const int g    = lane >> 2;
    const int t4   = lane & 3;
    const int arow = lane & 15;
    const int acol = (lane >> 4) << 2;
    const int row0 = blockIdx.x * 128;

    float acc[2][6][4];
#pragma unroll
    for (int mf = 0; mf < 2; mf++)
#pragma unroll
        for (int nf = 0; nf < 6; nf++)
#pragma unroll
            for (int i = 0; i < 4; i++) acc[mf][nf][i] = 0.f;

    // LDG index precompute
    const int xr0 = tid >> 3,  xc0 = (tid & 7) * 4;          // l=0
    const int xr1 = (tid + 512) >> 3, xc1 = xc0;             // l=1 (same c4 pattern)
    const int wr  = tid >> 4,  wc = (tid & 15) * 4;

    float4 rx0, rx1, rwq, rwk, rwv;

    // ---- prologue: LDG chunk 0, STS -> buf 0 ----
    rx0 = *reinterpret_cast<const float4*>(&x[(size_t)(row0 + xr0) * DD + xc0]);
    rx1 = *reinterpret_cast<const float4*>(&x[(size_t)(row0 + xr1) * DD + xc1]);
    rwq = *reinterpret_cast<const float4*>(&Wq[(size_t)wr * HS + wc]);
    rwk = *reinterpret_cast<const float4*>(&Wk[(size_t)wr * HS + wc]);
    rwv = *reinterpret_cast<const float4*>(&Wv[(size_t)wr * HS + wc]);
    {
        uint32_t* xb = xs;  // buf 0
        uint32_t* wb = ws;
        *reinterpret_cast<uint4*>(&xb[xr0 * PXS_P + xc0]) =
            make_uint4(f2tf(rx0.x), f2tf(rx0.y), f2tf(rx0.z), f2tf(rx0.w));
        *reinterpret_cast<uint4*>(&xb[xr1 * PXS_P + xc1]) =
            make_uint4(f2tf(rx1.x), f2tf(rx1.y), f2tf(rx1.z), f2tf(rx1.w));
        *reinterpret_cast<uint4*>(&wb[wr * PWS_P + wc]) =
            make_uint4(f2tf(rwq.x), f2tf(rwq.y), f2tf(rwq.z), f2tf(rwq.w));
        *reinterpret_cast<uint4*>(&wb[wr * PWS_P + 64 + wc]) =
            make_uint4(f2tf(rwk.x), f2tf(rwk.y), f2tf(rwk.z), f2tf(rwk.w));
        *reinterpret_cast<uint4*>(&wb[wr * PWS_P + 128 + wc]) =
            make_uint4(f2tf(rwv.x), f2tf(rwv.y), f2tf(rwv.z), f2tf(rwv.w));
    }
    __syncthreads();

    for (int ci = 0; ci < 32; ci++) {
        const int cur = ci & 1;
        const bool more = (ci + 1 < 32);

        // LDG chunk ci+1 (latency hidden under the MMA phase below)
        if (more) {
            const int kn = (ci + 1) * 32;
            rx0 = *reinterpret_cast<const float4*>(&x[(size_t)(row0 + xr0) * DD + kn + xc0]);
            rx1 = *reinterpret_cast<const float4*>(&x[(size_t)(row0 + xr1) * DD + kn + xc1]);
            rwq = *reinterpret_cast<const float4*>(&Wq[(size_t)(kn + wr) * HS + wc]);
            rwk = *reinterpret_cast<const float4*>(&Wk[(size_t)(kn + wr) * HS + wc]);
            rwv = *reinterpret_cast<const float4*>(&Wv[(size_t)(kn + wr) * HS + wc]);
        }

        // ---- MMA phase on buf cur ----
        const uint32_t xbb = smb + (cur * 128 * PXS_P) * 4;
        const uint32_t* wbc = ws + cur * 32 * PWS_P;
#pragma unroll
        for (int kf = 0; kf < 4; kf++) {
            int kb = kf * 8;
            uint32_t a0, a1, a2, a3, c0, c1, c2, c3;
            LDSM_X4(a0, a1, a2, a3,
                    xbb + ((wm * 32 + arow) * PXS_P + kb + acol) * 4);
            LDSM_X4(c0, c1, c2, c3,
                    xbb + ((wm * 32 + 16 + arow) * PXS_P + kb + acol) * 4);
#pragma unroll
            for (int nf = 0; nf < 6; nf++) {
                int nn = wn * 48 + nf * 8 + g;
                uint32_t b0 = wbc[(kb + t4) * PWS_P + nn];
                uint32_t b1 = wbc[(kb + t4 + 4) * PWS_P + nn];
                mma_tf32(acc[0][nf], a0, a1, a2, a3, b0, b1);
                mma_tf32(acc[1][nf], c0, c1, c2, c3, b0, b1);
            }
        }

        // ---- STS chunk ci+1 -> buf cur^1 ----
        if (more) {
            const int nx = cur ^ 1;
            uint32_t* xb = xs + nx * 128 * PXS_P;
            uint32_t* wb = ws + nx * 32 * PWS_P;
            *reinterpret_cast<uint4*>(&xb[xr0 * PXS_P + xc0]) =
                make_uint4(f2tf(rx0.x), f2tf(rx0.y), f2tf(rx0.z), f2tf(rx0.w));
            *reinterpret_cast<uint4*>(&xb[xr1 * PXS_P + xc1]) =
                make_uint4(f2tf(rx1.x), f2tf(rx1.y), f2tf(rx1.z), f2tf(rx1.w));
            *reinterpret_cast<uint4*>(&wb[wr * PWS_P + wc]) =
                make_uint4(f2tf(rwq.x), f2tf(rwq.y), f2tf(rwq.z), f2tf(rwq.w));
            *reinterpret_cast<uint4*>(&wb[wr * PWS_P + 64 + wc]) =
                make_uint4(f2tf(rwk.x), f2tf(rwk.y), f2tf(rwk.z), f2tf(rwk.w));
            *reinterpret_cast<uint4*>(&wb[wr * PWS_P + 128 + wc]) =
                make_uint4(f2tf(rwv.x), f2tf(rwv.y), f2tf(rwv.z), f2tf(rwv.w));
        }
        __syncthreads();
    }

    // ---- epilogue: bias add, route by n-range, Q scaled, V transposed ----
#pragma unroll
    for (int mf = 0; mf < 2; mf++) {
        const int r0 = row0 + wm * 32 + mf * 16 + g;   // rows r0, r0+8
        const int bat = r0 >> 11;
        const int trow = r0 & (TT - 1);
#pragma unroll
        for (int nf = 0; nf < 6; nf++) {
            const int ng = wn * 48 + nf * 8 + 2 * t4;
            const int mat = ng >> 6;
            const int col = ng & 63;
            const float v0 = acc[mf][nf][0], v1 = acc[mf][nf][1];
            const float v2 = acc[mf][nf][2], v3 = acc[mf][nf][3];
            if (mat == 0) {
                float b0 = bq[col], b1 = bq[col + 1];
                *reinterpret_cast<uint2*>(&g_Q[(size_t)r0 * HS + col]) =
                    make_uint2(f2tf((v0 + b0) * 0.125f), f2tf((v1 + b1) * 0.125f));
                *reinterpret_cast<uint2*>(&g_Q[(size_t)(r0 + 8) * HS + col]) =
                    make_uint2(f2tf((v2 + b0) * 0.125f), f2tf((v3 + b1) * 0.125f));
            } else if (mat == 1) {
                float b0 = bk[col], b1 = bk[col + 1];
                *reinterpret_cast<uint2*>(&g_K[(size_t)r0 * HS + col]) =
                    make_uint2(f2tf(v0 + b0), f2tf(v1 + b1));
                *reinterpret_cast<uint2*>(&g_K[(size_t)(r0 + 8) * HS + col]) =
                    make_uint2(f2tf(v2 + b0), f2tf(v3 + b1));
            } else {
                float b0 = bv[col], b1 = bv[col + 1];
                size_t vt = ((size_t)bat * HS + col) * TT + trow;
                g_V[vt]          = f2tf(v0 + b0);
                g_V[vt + TT]     = f2tf(v1 + b1);
                g_V[vt + 8]      = f2tf(v2 + b0);
                g_V[vt + TT + 8] = f2tf(v3 + b1);
            }
        }
    }
}

// ---------------------------------------------------------------------------
// Kernel 2: causal flash attention, split-K softmax, ldmatrix fragments.
// (unchanged from round 5 — passing at 57.2us)
// ---------------------------------------------------------------------------
#define KS_P 68
#define VT_P 68
#define PS_P 68
#define OFF_K  0
#define OFF_VT (2 * 64 * KS_P)
#define OFF_P  (OFF_VT + 2 * 64 * VT_P)
#define HALF_U32 (OFF_P + 64 * PS_P)
#define SMEM_BYTES (2 * HALF_U32 * 4)
#define NEG_BIG (-1e30f)

__global__ __launch_bounds__(512, 1) void flash_attn(float* __restrict__ out) {
    extern __shared__ uint32_t sm[];

    const int tid  = threadIdx.x;
    const int half = tid >> 8;
    const int ht   = tid & 255;
    const int lane = tid & 31;
    const int wid  = ht >> 5;
    const int wm   = wid & 3;
    const int wn   = wid >> 2;
    const int m0   = wm * 16;
    const int n0   = wn * 32;
    const int g    = lane >> 2;
    const int t4   = lane & 3;
    const int b    = blockIdx.y;
    const int barid = 1 + half;

    const int qt = half ? (31 - (int)blockIdx.x) : (int)blockIdx.x;
    const int q0 = qt * 64;
    const int nt = qt + 1;

    uint32_t* hsm = sm + half * HALF_U32;
    const uint32_t hbase =
        (uint32_t)__cvta_generic_to_shared(sm) + half * HALF_U32 * 4;
    const uint32_t kbase  = hbase + OFF_K * 4;
    const uint32_t vtbase = hbase + OFF_VT * 4;
    const uint32_t pbase  = hbase + OFF_P * 4;

    const int arow = lane & 15;
    const int acol = (lane >> 4) << 2;
    const int brow = (lane & 7) + ((lane >> 4) << 3);
    const int bcol = ((lane >> 3) & 1) << 2;

    const uint32_t* Qg = g_Q + ((size_t)b * TT + q0) * HS;
    const uint32_t* Kb = g_K + (size_t)b * TT * HS;
    const uint32_t* Vb = g_V + (size_t)b * HS * TT;

#pragma unroll
    for (int l = 0; l < 4; l++) {
        int f = ht + l * 256;
        int r = f >> 4, c4 = f & 15;
        CP_ASYNC16(pbase + (r * PS_P + c4 * 4) * 4, Qg + (size_t)r * HS + c4 * 4);
    }
    CP_COMMIT();
#pragma unroll
    for (int l = 0; l < 4; l++) {
        int f = ht + l * 256;
        int r = f >> 4, c4 = f & 15;
        CP_ASYNC16(kbase + (r * KS_P + c4 * 4) * 4, Kb + (size_t)r * HS + c4 * 4);
        CP_ASYNC16(vtbase + (r * VT_P + c4 * 4) * 4, Vb + (size_t)r * TT + c4 * 4);
    }
    CP_COMMIT();
    CP_WAIT(1);
    BARH(barid);

    uint32_t aq[8][4];
#pragma unroll
    for (int kf = 0; kf < 8; kf++) {
        uint32_t addr = pbase + (((m0 + arow) * PS_P) + kf * 8 + acol) * 4;
        LDSM_X4(aq[kf][0], aq[kf][1], aq[kf][2], aq[kf][3], addr);
    }

    float o[8][4];
#pragma unroll
    for (int nf = 0; nf < 8; nf++)
#pragma unroll
        for (int i = 0; i < 4; i++) o[nf][i] = 0.f;
    float mrow0 = NEG_BIG, mrow1 = NEG_BIG;
    float lrow0 = 0.f, lrow1 = 0.f;

    const int qg0 = q0 + m0 + g;
    const int qg1 = qg0 + 8;

    for (int it = 0; it < nt; it++) {
        const int cur = it & 1;
        BARH(barid);

        if (it + 1 < nt) {
            const int nx = cur ^ 1;
            const uint32_t* Kg = Kb + (size_t)(it + 1) * 64 * HS;
            const uint32_t* Vg = Vb + (size_t)(it + 1) * 64;
#pragma unroll
            for (int l = 0; l < 4; l++) {
                int f = ht + l * 256;
                int r = f >> 4, c4 = f & 15;
                CP_ASYNC16(kbase + ((nx * 64 + r) * KS_P + c4 * 4) * 4,
                           Kg + (size_t)r * HS + c4 * 4);
                CP_ASYNC16(vtbase + ((nx * 64 + r) * VT_P + c4 * 4) * 4,
                           Vg + (size_t)r * TT + c4 * 4);
            }
            CP_COMMIT();
            CP_WAIT(1);
        } else {
            CP_WAIT(0);
        }
        BARH(barid);

        const uint32_t kst  = kbase + cur * 64 * KS_P * 4;
        const uint32_t vtst = vtbase + cur * 64 * VT_P * 4;

        float s[4][4];
#pragma unroll
        for (int nf = 0; nf < 4; nf++)
#pragma unroll
            for (int i = 0; i < 4; i++) s[nf][i] = 0.f;

#pragma unroll
        for (int kf = 0; kf < 8; kf++) {
            int kb = kf * 8;
#pragma unroll
            for (int nfp = 0; nfp < 2; nfp++) {
                uint32_t b0, b1, b2, b3;
                uint32_t addr = kst +
                    ((n0 + nfp * 16 + brow) * KS_P + kb + bcol) * 4;
                LDSM_X4(b0, b1, b2, b3, addr);
                mma_tf32(s[nfp * 2],     aq[kf][0], aq[kf][1], aq[kf][2], aq[kf][3], b0, b1);
                mma_tf32(s[nfp * 2 + 1], aq[kf][0], aq[kf][1], aq[kf][2], aq[kf][3], b2, b3);
            }
        }

        const bool diag = (it == qt);
        const int j0 = it * 64;
        float rm0 = NEG_BIG, rm1 = NEG_BIG;
#pragma unroll
        for (int nf = 0; nf < 4; nf++) {
            if (diag) {
                int c = j0 + n0 + nf * 8 + 2 * t4;
                if (c > qg0)     s[nf][0] = NEG_BIG;
                if (c + 1 > qg0) s[nf][1] = NEG_BIG;
                if (c > qg1)     s[nf][2] = NEG_BIG;
                if (c + 1 > qg1) s[nf][3] = NEG_BIG;
            }
            rm0 = fmaxf(rm0, fmaxf(s[nf][0], s[nf][1]));
            rm1 = fmaxf(rm1, fmaxf(s[nf][2], s[nf][3]));
        }
        rm0 = fmaxf(rm0, __shfl_xor_sync(0xffffffffu, rm0, 1));
        rm0 = fmaxf(rm0, __shfl_xor_sync(0xffffffffu, rm0, 2));
        rm1 = fmaxf(rm1, __shfl_xor_sync(0xffffffffu, rm1, 1));
        rm1 = fmaxf(rm1, __shfl_xor_sync(0xffffffffu, rm1, 2));

        float mnew0 = fmaxf(mrow0, rm0);
        float mnew1 = fmaxf(mrow1, rm1);
        float alpha0 = __expf(mrow0 - mnew0);
        float alpha1 = __expf(mrow1 - mnew1);

        __syncwarp();
        float rs0 = 0.f, rs1 = 0.f;
#pragma unroll
        for (int nf = 0; nf < 4; nf++) {
            float p0 = __expf(s[nf][0] - mnew0);
            float p1 = __expf(s[nf][1] - mnew0);
            float p2 = __expf(s[nf][2] - mnew1);
            float p3 = __expf(s[nf][3] - mnew1);
            rs0 += p0 + p1;
            rs1 += p2 + p3;
            int c0 = n0 + nf * 8 + 2 * t4;
            *reinterpret_cast<uint2*>(&hsm[OFF_P + (m0 + g) * PS_P + c0]) =
                make_uint2(f2tf(p0), f2tf(p1));
            *reinterpret_cast<uint2*>(&hsm[OFF_P + (m0 + g + 8) * PS_P + c0]) =
                make_uint2(f2tf(p2), f2tf(p3));
        }
        rs0 += __shfl_xor_sync(0xffffffffu, rs0, 1);
        rs0 += __shfl_xor_sync(0xffffffffu, rs0, 2);
        rs1 += __shfl_xor_sync(0xffffffffu, rs1, 1);
        rs1 += __shfl_xor_sync(0xffffffffu, rs1, 2);

        lrow0 = lrow0 * alpha0 + rs0;  mrow0 = mnew0;
        lrow1 = lrow1 * alpha1 + rs1;  mrow1 = mnew1;
#pragma unroll
        for (int nf = 0; nf < 8; nf++) {
            o[nf][0] *= alpha0; o[nf][1] *= alpha0;
            o[nf][2] *= alpha1; o[nf][3] *= alpha1;
        }
        __syncwarp();

#pragma unroll
        for (int kf = 0; kf < 4; kf++) {
            int kb = kf * 8;
            uint32_t a0, a1, a2, a3;
            uint32_t aaddr = pbase + ((m0 + arow) * PS_P + n0 + kb + acol) * 4;
            LDSM_X4(a0, a1, a2, a3, aaddr);
#pragma unroll
            for (int nfp = 0; nfp < 4; nfp++) {
                uint32_t b0, b1, b2, b3;
                uint32_t vaddr = vtst +
                    ((nfp * 16 + brow) * VT_P + n0 + kb + bcol) * 4;
                LDSM_X4(b0, b1, b2, b3, vaddr);
                mma_tf32(o[nfp * 2],     a0, a1, a2, a3, b0, b1);
                mma_tf32(o[nfp * 2 + 1], a0, a1, a2, a3, b2, b3);
            }
        }
    }

    float* Pf = reinterpret_cast<float*>(hsm + OFF_P);
    BARH(barid);
    if (wn == 1) {
#pragma unroll
        for (int nf = 0; nf < 8; nf++) {
            int c0 = nf * 8 + 2 * t4;
            Pf[(m0 + g) * PS_P + c0]         = o[nf][0];
            Pf[(m0 + g) * PS_P + c0 + 1]     = o[nf][1];
            Pf[(m0 + g + 8) * PS_P + c0]     = o[nf][2];
            Pf[(m0 + g + 8) * PS_P + c0 + 1] = o[nf][3];
        }
        if (t4 == 0) {
            Pf[(m0 + g) * PS_P + 64] = mrow0;
            Pf[(m0 + g) * PS_P + 65] = lrow0;
            Pf[(m0 + g + 8) * PS_P + 64] = mrow1;
            Pf[(m0 + g + 8) * PS_P + 65] = lrow1;
        }
    }
    BARH(barid);
    if (wn == 0) {
        float m1_0 = Pf[(m0 + g) * PS_P + 64];
        float l1_0 = Pf[(m0 + g) * PS_P + 65];
        float m1_1 = Pf[(m0 + g + 8) * PS_P + 64];
        float l1_1 = Pf[(m0 + g + 8) * PS_P + 65];

        float M0 = fmaxf(mrow0, m1_0);
        float w00 = __expf(mrow0 - M0), w10 = __expf(m1_0 - M0);
        float inv0 = 1.f / (lrow0 * w00 + l1_0 * w10);
        float s00 = w00 * inv0, s10 = w10 * inv0;

        float M1 = fmaxf(mrow1, m1_1);
        float w01 = __expf(mrow1 - M1), w11 = __expf(m1_1 - M1);
        float inv1 = 1.f / (lrow1 * w01 + l1_1 * w11);
        float s01 = w01 * inv1, s11 = w11 * inv1;

        const int row = q0 + m0 + g;
#pragma unroll
        for (int nf = 0; nf < 8; nf++) {
            int c0 = nf * 8 + 2 * t4;
            float u0 = o[nf][0] * s00 + Pf[(m0 + g) * PS_P + c0]     * s10;
            float u1 = o[nf][1] * s00 + Pf[(m0 + g) * PS_P + c0 + 1] * s10;
            float u2 = o[nf][2] * s01 + Pf[(m0 + g + 8) * PS_P + c0]     * s11;
            float u3 = o[nf][3] * s01 + Pf[(m0 + g + 8) * PS_P + c0 + 1] * s11;
            *reinterpret_cast<float2*>(&out[((size_t)b * TT + row) * HS + c0]) =
                make_float2(u0, u1);
            *reinterpret_cast<float2*>(&out[((size_t)b * TT + row + 8) * HS + c0]) =
                make_float2(u2, u3);
        }
    }
}

// ---------------------------------------------------------------------------
extern "C" void kernel_launch(void* const* d_in, const int* in_sizes, int n_in,
                              void* d_out, int out_size) {
    const float* x  = (const float*)d_in[0];
    const float* Wq = (const float*)d_in[1];
    const float* bq = (const float*)d_in[2];
    const float* Wk = (const float*)d_in[3];
    const float* bk = (const float*)d_in[4];
    const float* Wv = (const float*)d_in[5];
    const float* bv = (const float*)d_in[6];
    float* out = (float*)d_out;

    cudaFuncSetAttribute(qkv_proj, cudaFuncAttributeMaxDynamicSharedMemorySize,
                         PSMEM_BYTES);
    cudaFuncSetAttribute(flash_attn, cudaFuncAttributeMaxDynamicSharedMemorySize,
                         SMEM_BYTES);

    qkv_proj<<<(BB * TT) / 128, 512, PSMEM_BYTES>>>(x, Wq, bq, Wk, bk, Wv, bv);
    flash_attn<<<dim3(16, BB), 512, SMEM_BYTES>>>(out);
}

// round 9
// speedup vs baseline: 1.3073x; 1.3073x over previous
#include <cuda_runtime.h>
#include <math.h>
#include <stdint.h>

#define BB 8
#define TT 2048
#define DD 1024
#define HS 64

// Q,K: [b][t][h] tf32 bits.  V: TRANSPOSED [b][h][t] tf32 bits.
__device__ uint32_t g_Q[BB * TT * HS];
__device__ uint32_t g_K[BB * TT * HS];
__device__ uint32_t g_V[BB * TT * HS];
// W pre-converted to tf32, interleaved [k][Q|K|V = 192 cols]
__device__ uint32_t g_W[DD * 192];

// ---------------------------------------------------------------------------
__device__ __forceinline__ uint32_t f2tf(float f) {
    uint32_t u;
    asm("cvt.rna.tf32.f32 %0, %1;" : "=r"(u) : "f"(f));
    return u;
}
__device__ __forceinline__ uint32_t f2tf_bits(uint32_t bits) {
    uint32_t u;
    asm("cvt.rna.tf32.f32 %0, %1;" : "=r"(u) : "f"(__uint_as_float(bits)));
    return u;
}

__device__ __forceinline__ void mma_tf32(float* d,
                                         uint32_t a0, uint32_t a1, uint32_t a2, uint32_t a3,
                                         uint32_t b0, uint32_t b1) {
    asm volatile(
        "mma.sync.aligned.m16n8k8.row.col.f32.tf32.tf32.f32 "
        "{%0,%1,%2,%3}, {%4,%5,%6,%7}, {%8,%9}, {%0,%1,%2,%3};\n"
        : "+f"(d[0]), "+f"(d[1]), "+f"(d[2]), "+f"(d[3])
        : "r"(a0), "r"(a1), "r"(a2), "r"(a3), "r"(b0), "r"(b1));
}

#define LDSM_X4(r0, r1, r2, r3, addr) \
    asm volatile("ldmatrix.sync.aligned.m8n8.x4.shared.b16 {%0,%1,%2,%3}, [%4];" \
                 : "=r"(r0), "=r"(r1), "=r"(r2), "=r"(r3) : "r"(addr))

#define CP_ASYNC16(dst_bytes, src_ptr) \
    asm volatile("cp.async.cg.shared.global [%0], [%1], 16;\n" \
                 :: "r"(dst_bytes), "l"(src_ptr))
#define CP_COMMIT() asm volatile("cp.async.commit_group;\n" ::: "memory")
#define CP_WAIT(n)  asm volatile("cp.async.wait_group %0;\n" :: "n"(n) : "memory")

#define BARH(id) asm volatile("bar.sync %0, 256;" :: "r"(id) : "memory")

// ---------------------------------------------------------------------------
// Kernel 0: one-shot W conversion -> g_W[k][192] tf32 bits.
// 49152 threads, each handles one float4 of one matrix.
// ---------------------------------------------------------------------------
__global__ __launch_bounds__(256) void wcvt(const float* __restrict__ Wq,
                                            const float* __restrict__ Wk,
                                            const float* __restrict__ Wv) {
    int gid = blockIdx.x * 256 + threadIdx.x;      // 0 .. 49151
    int k   = gid / 48;
    int c4  = gid % 48;
    int mat = c4 >> 4;
    int colg = (c4 & 15) * 4;
    const float* src = (mat == 0) ? Wq : (mat == 1) ? Wk : Wv;
    float4 v = *reinterpret_cast<const float4*>(&src[(size_t)k * HS + colg]);
    *reinterpret_cast<uint4*>(&g_W[(size_t)k * 192 + mat * 64 + colg]) =
        make_uint4(f2tf(v.x), f2tf(v.y), f2tf(v.z), f2tf(v.w));
}

// ---------------------------------------------------------------------------
// Kernel 1: fused QKV projection [16384 x 1024] x [1024 x 192].
// 256 blocks x 256 thr (8 warps: 4m x 2n; warp tile 16 x 96).
// 3-stage cp.async pipeline, k-chunk 16; x raw fp32 (cvt after ldmatrix),
// W pre-converted. 52KB dynamic smem -> 2 blocks/SM.
// ---------------------------------------------------------------------------
#define PX_P 20
#define PW_P 196
#define PST_X (64 * PX_P)
#define PST_W (16 * PW_P)
#define POFF_W (3 * PST_X)
#define PSMEM_U32 (POFF_W + 3 * PST_W)
#define PSMEM_BYTES (PSMEM_U32 * 4)

__global__ __launch_bounds__(256, 2) void qkv_proj(
    const float* __restrict__ x,
    const float* __restrict__ bq, const float* __restrict__ bk,
    const float* __restrict__ bv) {
    extern __shared__ uint32_t psm[];
    const uint32_t smb = (uint32_t)__cvta_generic_to_shared(psm);

    const int tid  = threadIdx.x;
    const int lane = tid & 31;
    const int wid  = tid >> 5;
    const int wm   = wid & 3;
    const int wn   = wid >> 2;
    const int g    = lane >> 2;
    const int t4   = lane & 3;
    const int arow = lane & 15;
    const int acol = (lane >> 4) << 2;
    const int row0 = blockIdx.x * 64;

    // cp.async index precompute
    const int xr = tid >> 2, xc = (tid & 3) * 4;              // x: 1 per thread
    int wrow[3], wcol[3];
#pragma unroll
    for (int l = 0; l < 3; l++) {
        int f = tid + l * 256;
        wrow[l] = f / 48;
        wcol[l] = (f % 48) * 4;
    }

    float acc[12][4];
#pragma unroll
    for (int nf = 0; nf < 12; nf++)
#pragma unroll
        for (int i = 0; i < 4; i++) acc[nf][i] = 0.f;

    // issue chunk ci into slot
#define PROJ_ISSUE(ci, slot)                                                   \
    do {                                                                       \
        int k0 = (ci) * 16;                                                    \
        CP_ASYNC16(smb + ((slot) * PST_X + xr * PX_P + xc) * 4,                \
                   x + (size_t)(row0 + xr) * DD + k0 + xc);                    \
        _Pragma("unroll")                                                      \
        for (int l = 0; l < 3; l++) {                                          \
            CP_ASYNC16(smb + (POFF_W + (slot) * PST_W + wrow[l] * PW_P +       \
                              wcol[l]) * 4,                                    \
                       g_W + (size_t)(k0 + wrow[l]) * 192 + wcol[l]);          \
        }                                                                      \
    } while (0)

    PROJ_ISSUE(0, 0); CP_COMMIT();
    PROJ_ISSUE(1, 1); CP_COMMIT();

    for (int ci = 0; ci < 64; ci++) {
        const int s = ci % 3;
        CP_WAIT(1);
        __syncthreads();
        if (ci + 2 < 64) {
            const int ns = (ci + 2) % 3;
            PROJ_ISSUE(ci + 2, ns);
        }
        CP_COMMIT();

        const uint32_t xbb = smb + (s * PST_X) * 4;
        const uint32_t* wb = psm + POFF_W + s * PST_W;
#pragma unroll
        for (int kf = 0; kf < 2; kf++) {
            const int kb = kf * 8;
            uint32_t a0, a1, a2, a3;
            LDSM_X4(a0, a1, a2, a3,
                    xbb + ((wm * 16 + arow) * PX_P + kb + acol) * 4);
            a0 = f2tf_bits(a0); a1 = f2tf_bits(a1);
            a2 = f2tf_bits(a2); a3 = f2tf_bits(a3);
#pragma unroll
            for (int nf = 0; nf < 12; nf++) {
                const int nn = wn * 96 + nf * 8 + g;
                uint32_t b0 = wb[(kb + t4) * PW_P + nn];
                uint32_t b1 = wb[(kb + t4 + 4) * PW_P + nn];
                mma_tf32(acc[nf], a0, a1, a2, a3, b0, b1);
            }
        }
    }

    // ---- epilogue: bias add, route by n-range, Q scaled, V transposed ----
    const int r0 = row0 + wm * 16 + g;
    const int bat = r0 >> 11;
    const int trow = r0 & (TT - 1);
#pragma unroll
    for (int nf = 0; nf < 12; nf++) {
        const int ng = wn * 96 + nf * 8 + 2 * t4;
        const int mat = ng >> 6;
        const int col = ng & 63;
        const float v0 = acc[nf][0], v1 = acc[nf][1];
        const float v2 = acc[nf][2], v3 = acc[nf][3];
        if (mat == 0) {
            float b0 = bq[col], b1 = bq[col + 1];
            *reinterpret_cast<uint2*>(&g_Q[(size_t)r0 * HS + col]) =
                make_uint2(f2tf((v0 + b0) * 0.125f), f2tf((v1 + b1) * 0.125f));
            *reinterpret_cast<uint2*>(&g_Q[(size_t)(r0 + 8) * HS + col]) =
                make_uint2(f2tf((v2 + b0) * 0.125f), f2tf((v3 + b1) * 0.125f));
        } else if (mat == 1) {
            float b0 = bk[col], b1 = bk[col + 1];
            *reinterpret_cast<uint2*>(&g_K[(size_t)r0 * HS + col]) =
                make_uint2(f2tf(v0 + b0), f2tf(v1 + b1));
            *reinterpret_cast<uint2*>(&g_K[(size_t)(r0 + 8) * HS + col]) =
                make_uint2(f2tf(v2 + b0), f2tf(v3 + b1));
        } else {
            float b0 = bv[col], b1 = bv[col + 1];
            size_t vt = ((size_t)bat * HS + col) * TT + trow;
            g_V[vt]          = f2tf(v0 + b0);
            g_V[vt + TT]     = f2tf(v1 + b1);
            g_V[vt + 8]      = f2tf(v2 + b0);
            g_V[vt + TT + 8] = f2tf(v3 + b1);
        }
    }
}

// ---------------------------------------------------------------------------
// Kernel 2: causal flash attention (round-5 version, verbatim: 57.2us).
// ---------------------------------------------------------------------------
#define KS_P 68
#define VT_P 68
#define PS_P 68
#define OFF_K  0
#define OFF_VT (2 * 64 * KS_P)
#define OFF_P  (OFF_VT + 2 * 64 * VT_P)
#define HALF_U32 (OFF_P + 64 * PS_P)
#define SMEM_BYTES (2 * HALF_U32 * 4)
#define NEG_BIG (-1e30f)

__global__ __launch_bounds__(512, 1) void flash_attn(float* __restrict__ out) {
    extern __shared__ uint32_t sm[];

    const int tid  = threadIdx.x;
    const int half = tid >> 8;
    const int ht   = tid & 255;
    const int lane = tid & 31;
    const int wid  = ht >> 5;
    const int wm   = wid & 3;
    const int wn   = wid >> 2;
    const int m0   = wm * 16;
    const int n0   = wn * 32;
    const int g    = lane >> 2;
    const int t4   = lane & 3;
    const int b    = blockIdx.y;
    const int barid = 1 + half;

    const int qt = half ? (31 - (int)blockIdx.x) : (int)blockIdx.x;
    const int q0 = qt * 64;
    const int nt = qt + 1;

    uint32_t* hsm = sm + half * HALF_U32;
    const uint32_t hbase =
        (uint32_t)__cvta_generic_to_shared(sm) + half * HALF_U32 * 4;
    const uint32_t kbase  = hbase + OFF_K * 4;
    const uint32_t vtbase = hbase + OFF_VT * 4;
    const uint32_t pbase  = hbase + OFF_P * 4;

    const int arow = lane & 15;
    const int acol = (lane >> 4) << 2;
    const int brow = (lane & 7) + ((lane >> 4) << 3);
    const int bcol = ((lane >> 3) & 1) << 2;

    const uint32_t* Qg = g_Q + ((size_t)b * TT + q0) * HS;
    const uint32_t* Kb = g_K + (size_t)b * TT * HS;
    const uint32_t* Vb = g_V + (size_t)b * HS * TT;

#pragma unroll
    for (int l = 0; l < 4; l++) {
        int f = ht + l * 256;
        int r = f >> 4, c4 = f & 15;
        CP_ASYNC16(pbase + (r * PS_P + c4 * 4) * 4, Qg + (size_t)r * HS + c4 * 4);
    }
    CP_COMMIT();
#pragma unroll
    for (int l = 0; l < 4; l++) {
        int f = ht + l * 256;
        int r = f >> 4, c4 = f & 15;
        CP_ASYNC16(kbase + (r * KS_P + c4 * 4) * 4, Kb + (size_t)r * HS + c4 * 4);
        CP_ASYNC16(vtbase + (r * VT_P + c4 * 4) * 4, Vb + (size_t)r * TT + c4 * 4);
    }
    CP_COMMIT();
    CP_WAIT(1);
    BARH(barid);

    uint32_t aq[8][4];
#pragma unroll
    for (int kf = 0; kf < 8; kf++) {
        uint32_t addr = pbase + (((m0 + arow) * PS_P) + kf * 8 + acol) * 4;
        LDSM_X4(aq[kf][0], aq[kf][1], aq[kf][2], aq[kf][3], addr);
    }

    float o[8][4];
#pragma unroll
    for (int nf = 0; nf < 8; nf++)
#pragma unroll
        for (int i = 0; i < 4; i++) o[nf][i] = 0.f;
    float mrow0 = NEG_BIG, mrow1 = NEG_BIG;
    float lrow0 = 0.f, lrow1 = 0.f;

    const int qg0 = q0 + m0 + g;
    const int qg1 = qg0 + 8;

    for (int it = 0; it < nt; it++) {
        const int cur = it & 1;
        BARH(barid);

        if (it + 1 < nt) {
            const int nx = cur ^ 1;
            const uint32_t* Kg = Kb + (size_t)(it + 1) * 64 * HS;
            const uint32_t* Vg = Vb + (size_t)(it + 1) * 64;
#pragma unroll
            for (int l = 0; l < 4; l++) {
                int f = ht + l * 256;
                int r = f >> 4, c4 = f & 15;
                CP_ASYNC16(kbase + ((nx * 64 + r) * KS_P + c4 * 4) * 4,
                           Kg + (size_t)r * HS + c4 * 4);
                CP_ASYNC16(vtbase + ((nx * 64 + r) * VT_P + c4 * 4) * 4,
                           Vg + (size_t)r * TT + c4 * 4);
            }
            CP_COMMIT();
            CP_WAIT(1);
        } else {
            CP_WAIT(0);
        }
        BARH(barid);

        const uint32_t kst  = kbase + cur * 64 * KS_P * 4;
        const uint32_t vtst = vtbase + cur * 64 * VT_P * 4;

        float s[4][4];
#pragma unroll
        for (int nf = 0; nf < 4; nf++)
#pragma unroll
            for (int i = 0; i < 4; i++) s[nf][i] = 0.f;

#pragma unroll
        for (int kf = 0; kf < 8; kf++) {
            int kb = kf * 8;
#pragma unroll
            for (int nfp = 0; nfp < 2; nfp++) {
                uint32_t b0, b1, b2, b3;
                uint32_t addr = kst +
                    ((n0 + nfp * 16 + brow) * KS_P + kb + bcol) * 4;
                LDSM_X4(b0, b1, b2, b3, addr);
                mma_tf32(s[nfp * 2],     aq[kf][0], aq[kf][1], aq[kf][2], aq[kf][3], b0, b1);
                mma_tf32(s[nfp * 2 + 1], aq[kf][0], aq[kf][1], aq[kf][2], aq[kf][3], b2, b3);
            }
        }

        const bool diag = (it == qt);
        const int j0 = it * 64;
        float rm0 = NEG_BIG, rm1 = NEG_BIG;
#pragma unroll
        for (int nf = 0; nf < 4; nf++) {
            if (diag) {
                int c = j0 + n0 + nf * 8 + 2 * t4;
                if (c > qg0)     s[nf][0] = NEG_BIG;
                if (c + 1 > qg0) s[nf][1] = NEG_BIG;
                if (c > qg1)     s[nf][2] = NEG_BIG;
                if (c + 1 > qg1) s[nf][3] = NEG_BIG;
            }
            rm0 = fmaxf(rm0, fmaxf(s[nf][0], s[nf][1]));
            rm1 = fmaxf(rm1, fmaxf(s[nf][2], s[nf][3]));
        }
        rm0 = fmaxf(rm0, __shfl_xor_sync(0xffffffffu, rm0, 1));
        rm0 = fmaxf(rm0, __shfl_xor_sync(0xffffffffu, rm0, 2));
        rm1 = fmaxf(rm1, __shfl_xor_sync(0xffffffffu, rm1, 1));
        rm1 = fmaxf(rm1, __shfl_xor_sync(0xffffffffu, rm1, 2));

        float mnew0 = fmaxf(mrow0, rm0);
        float mnew1 = fmaxf(mrow1, rm1);
        float alpha0 = __expf(mrow0 - mnew0);
        float alpha1 = __expf(mrow1 - mnew1);

        __syncwarp();
        float rs0 = 0.f, rs1 = 0.f;
#pragma unroll
        for (int nf = 0; nf < 4; nf++) {
            float p0 = __expf(s[nf][0] - mnew0);
            float p1 = __expf(s[nf][1] - mnew0);
            float p2 = __expf(s[nf][2] - mnew1);
            float p3 = __expf(s[nf][3] - mnew1);
            rs0 += p0 + p1;
            rs1 += p2 + p3;
            int c0 = n0 + nf * 8 + 2 * t4;
            *reinterpret_cast<uint2*>(&hsm[OFF_P + (m0 + g) * PS_P + c0]) =
                make_uint2(f2tf(p0), f2tf(p1));
            *reinterpret_cast<uint2*>(&hsm[OFF_P + (m0 + g + 8) * PS_P + c0]) =
                make_uint2(f2tf(p2), f2tf(p3));
        }
        rs0 += __shfl_xor_sync(0xffffffffu, rs0, 1);
        rs0 += __shfl_xor_sync(0xffffffffu, rs0, 2);
        rs1 += __shfl_xor_sync(0xffffffffu, rs1, 1);
        rs1 += __shfl_xor_sync(0xffffffffu, rs1, 2);

        lrow0 = lrow0 * alpha0 + rs0;  mrow0 = mnew0;
        lrow1 = lrow1 * alpha1 + rs1;  mrow1 = mnew1;
#pragma unroll
        for (int nf = 0; nf < 8; nf++) {
            o[nf][0] *= alpha0; o[nf][1] *= alpha0;
            o[nf][2] *= alpha1; o[nf][3] *= alpha1;
        }
        __syncwarp();

#pragma unroll
        for (int kf = 0; kf < 4; kf++) {
            int kb = kf * 8;
            uint32_t a0, a1, a2, a3;
            uint32_t aaddr = pbase + ((m0 + arow) * PS_P + n0 + kb + acol) * 4;
            LDSM_X4(a0, a1, a2, a3, aaddr);
#pragma unroll
            for (int nfp = 0; nfp < 4; nfp++) {
                uint32_t b0, b1, b2, b3;
                uint32_t vaddr = vtst +
                    ((nfp * 16 + brow) * VT_P + n0 + kb + bcol) * 4;
                LDSM_X4(b0, b1, b2, b3, vaddr);
                mma_tf32(o[nfp * 2],     a0, a1, a2, a3, b0, b1);
                mma_tf32(o[nfp * 2 + 1], a0, a1, a2, a3, b2, b3);
            }
        }
    }

    float* Pf = reinterpret_cast<float*>(hsm + OFF_P);
    BARH(barid);
    if (wn == 1) {
#pragma unroll
        for (int nf = 0; nf < 8; nf++) {
            int c0 = nf * 8 + 2 * t4;
            Pf[(m0 + g) * PS_P + c0]         = o[nf][0];
            Pf[(m0 + g) * PS_P + c0 + 1]     = o[nf][1];
            Pf[(m0 + g + 8) * PS_P + c0]     = o[nf][2];
            Pf[(m0 + g + 8) * PS_P + c0 + 1] = o[nf][3];
        }
        if (t4 == 0) {
            Pf[(m0 + g) * PS_P + 64] = mrow0;
            Pf[(m0 + g) * PS_P + 65] = lrow0;
            Pf[(m0 + g + 8) * PS_P + 64] = mrow1;
            Pf[(m0 + g + 8) * PS_P + 65] = lrow1;
        }
    }
    BARH(barid);
    if (wn == 0) {
        float m1_0 = Pf[(m0 + g) * PS_P + 64];
        float l1_0 = Pf[(m0 + g) * PS_P + 65];
        float m1_1 = Pf[(m0 + g + 8) * PS_P + 64];
        float l1_1 = Pf[(m0 + g + 8) * PS_P + 65];

        float M0 = fmaxf(mrow0, m1_0);
        float w00 = __expf(mrow0 - M0), w10 = __expf(m1_0 - M0);
        float inv0 = 1.f / (lrow0 * w00 + l1_0 * w10);
        float s00 = w00 * inv0, s10 = w10 * inv0;

        float M1 = fmaxf(mrow1, m1_1);
        float w01 = __expf(mrow1 - M1), w11 = __expf(m1_1 - M1);
        float inv1 = 1.f / (lrow1 * w01 + l1_1 * w11);
        float s01 = w01 * inv1, s11 = w11 * inv1;

        const int row = q0 + m0 + g;
#pragma unroll
        for (int nf = 0; nf < 8; nf++) {
            int c0 = nf * 8 + 2 * t4;
            float u0 = o[nf][0] * s00 + Pf[(m0 + g) * PS_P + c0]     * s10;
            float u1 = o[nf][1] * s00 + Pf[(m0 + g) * PS_P + c0 + 1] * s10;
            float u2 = o[nf][2] * s01 + Pf[(m0 + g + 8) * PS_P + c0]     * s11;
            float u3 = o[nf][3] * s01 + Pf[(m0 + g + 8) * PS_P + c0 + 1] * s11;
            *reinterpret_cast<float2*>(&out[((size_t)b * TT + row) * HS + c0]) =
                make_float2(u0, u1);
            *reinterpret_cast<float2*>(&out[((size_t)b * TT + row + 8) * HS + c0]) =
                make_float2(u2, u3);
        }
    }
}

// ---------------------------------------------------------------------------
extern "C" void kernel_launch(void* const* d_in, const int* in_sizes, int n_in,
                              void* d_out, int out_size) {
    const float* x  = (const float*)d_in[0];
    const float* Wq = (const float*)d_in[1];
    const float* bq = (const float*)d_in[2];
    const float* Wk = (const float*)d_in[3];
    const float* bk = (const float*)d_in[4];
    const float* Wv = (const float*)d_in[5];
    const float* bv = (const float*)d_in[6];
    float* out = (float*)d_out;

    cudaFuncSetAttribute(qkv_proj, cudaFuncAttributeMaxDynamicSharedMemorySize,
                         PSMEM_BYTES);
    cudaFuncSetAttribute(flash_attn, cudaFuncAttributeMaxDynamicSharedMemorySize,
                         SMEM_BYTES);

    wcvt<<<192, 256>>>(Wq, Wk, Wv);
    qkv_proj<<<(BB * TT) / 64, 256, PSMEM_BYTES>>>(x, bq, bk, bv);
    flash_attn<<<dim3(16, BB), 512, SMEM_BYTES>>>(out);
}